// round 3
// baseline (speedup 1.0000x reference)
#include <cuda_runtime.h>
#include <cstdint>

#define N_NODES 100000
#define IN_CH   512
#define HID     16
#define OUT_CH  64

// ---------------- device scratch (static, no allocation) ----------------
__device__ float g_dinv[N_NODES];          // deg -> dinv in place
__device__ float g_h1[N_NODES * HID];      // layer1 linear out, then relu'd hidden
__device__ float g_agg[N_NODES * HID];     // aggregation buffer (reused both layers)

// ---------------- kernels ----------------
__global__ void k_init_deg(int n) {
    int i = blockIdx.x * blockDim.x + threadIdx.x;
    if (i < n) g_dinv[i] = 1.0f;  // self loop
}

__global__ void k_zero_agg(int n4) {
    int i = blockIdx.x * blockDim.x + threadIdx.x;
    if (i < n4) reinterpret_cast<float4*>(g_agg)[i] = make_float4(0.f, 0.f, 0.f, 0.f);
}

__global__ void k_count_deg(const int* __restrict__ dst, int e) {
    int i = blockIdx.x * blockDim.x + threadIdx.x;
    if (i < e) atomicAdd(&g_dinv[dst[i]], 1.0f);
}

__global__ void k_finalize_dinv(int n) {
    int i = blockIdx.x * blockDim.x + threadIdx.x;
    if (i < n) g_dinv[i] = rsqrtf(g_dinv[i]);
}

// GEMM1: h1 = x @ W1   (n x 512) @ (512 x 16)
// Block: 256 threads, tile 256 rows x 16 hid. Each thread: 4 rows x 4 hid.
#define XT_STRIDE 260  // 16B-aligned stride (260*4 % 16 == 0), breaks bank conflicts
__global__ void __launch_bounds__(256) k_gemm1(const float* __restrict__ x,
                                               const float* __restrict__ W, int n) {
    __shared__ __align__(16) float xT[16 * XT_STRIDE];  // [k][row]
    __shared__ __align__(16) float Wc[16 * HID];        // [k][j]

    const int t = threadIdx.x;
    const int rowBase = blockIdx.x * 256;
    const int jg = t & 3;   // hid group (4 cols)
    const int rg = t >> 2;  // row group (4 rows), 0..63

    float acc[4][4];
#pragma unroll
    for (int r = 0; r < 4; r++)
#pragma unroll
        for (int j = 0; j < 4; j++) acc[r][j] = 0.f;

    for (int kk = 0; kk < IN_CH; kk += 16) {
        // stage W chunk: Wc[k][j]
        Wc[t] = W[(kk + (t >> 4)) * HID + (t & 15)];
        // stage x tile transposed: each thread loads one float4 along k, 4 passes
#pragma unroll
        for (int p = 0; p < 4; p++) {
            int rlocal = (t >> 2) + p * 64;
            int k4 = (t & 3) * 4;
            int grow = rowBase + rlocal;
            float4 v = make_float4(0.f, 0.f, 0.f, 0.f);
            if (grow < n)
                v = *reinterpret_cast<const float4*>(&x[(size_t)grow * IN_CH + kk + k4]);
            xT[(k4 + 0) * XT_STRIDE + rlocal] = v.x;
            xT[(k4 + 1) * XT_STRIDE + rlocal] = v.y;
            xT[(k4 + 2) * XT_STRIDE + rlocal] = v.z;
            xT[(k4 + 3) * XT_STRIDE + rlocal] = v.w;
        }
        __syncthreads();
#pragma unroll
        for (int k = 0; k < 16; k++) {
            float4 xv = *reinterpret_cast<const float4*>(&xT[k * XT_STRIDE + rg * 4]);
            float4 wv = *reinterpret_cast<const float4*>(&Wc[k * HID + jg * 4]);
            acc[0][0] += xv.x * wv.x; acc[0][1] += xv.x * wv.y; acc[0][2] += xv.x * wv.z; acc[0][3] += xv.x * wv.w;
            acc[1][0] += xv.y * wv.x; acc[1][1] += xv.y * wv.y; acc[1][2] += xv.y * wv.z; acc[1][3] += xv.y * wv.w;
            acc[2][0] += xv.z * wv.x; acc[2][1] += xv.z * wv.y; acc[2][2] += xv.z * wv.z; acc[2][3] += xv.z * wv.w;
            acc[3][0] += xv.w * wv.x; acc[3][1] += xv.w * wv.y; acc[3][2] += xv.w * wv.z; acc[3][3] += xv.w * wv.w;
        }
        __syncthreads();
    }
#pragma unroll
    for (int r = 0; r < 4; r++) {
        int grow = rowBase + rg * 4 + r;
        if (grow < n) {
            float4 o = make_float4(acc[r][0], acc[r][1], acc[r][2], acc[r][3]);
            reinterpret_cast<float4*>(&g_h1[(size_t)grow * HID])[jg] = o;
        }
    }
}

// edge aggregation: g_agg[dst] += g_h1[src] * (dinv[src]*dinv[dst]), 16 floats/edge
__global__ void k_aggregate(const int* __restrict__ src,
                            const int* __restrict__ dst, int e) {
    int i = blockIdx.x * blockDim.x + threadIdx.x;
    if (i >= e) return;
    int s = src[i];
    int d = dst[i];
    float w = g_dinv[s] * g_dinv[d];
    const float4* hp = reinterpret_cast<const float4*>(&g_h1[(size_t)s * HID]);
    float* op = &g_agg[(size_t)d * HID];
#pragma unroll
    for (int q = 0; q < 4; q++) {
        float4 v = hp[q];
        atomicAdd(op + q * 4 + 0, v.x * w);
        atomicAdd(op + q * 4 + 1, v.y * w);
        atomicAdd(op + q * 4 + 2, v.z * w);
        atomicAdd(op + q * 4 + 3, v.w * w);
    }
}

// epilogue1: h1 = relu(agg + h1*dinv^2 + b1)   (self-loop folded in here)
__global__ void k_epilogue1(const float* __restrict__ b1, int n) {
    int idx = blockIdx.x * blockDim.x + threadIdx.x;  // over n*4 float4 groups
    if (idx >= n * 4) return;
    int node = idx >> 2, q = idx & 3;
    float di = g_dinv[node];
    float sl = di * di;
    float4 a = reinterpret_cast<const float4*>(g_agg)[idx];
    float4 h = reinterpret_cast<const float4*>(g_h1)[idx];
    float4 b = reinterpret_cast<const float4*>(b1)[q];
    float4 r;
    r.x = fmaxf(a.x + h.x * sl + b.x, 0.f);
    r.y = fmaxf(a.y + h.y * sl + b.y, 0.f);
    r.z = fmaxf(a.z + h.z * sl + b.z, 0.f);
    r.w = fmaxf(a.w + h.w * sl + b.w, 0.f);
    reinterpret_cast<float4*>(g_h1)[idx] = r;
}

// final: t = agg + h1*dinv^2 (16-dim aggregated hidden); y = t @ W2 + b2; out = log_softmax(y)
__global__ void __launch_bounds__(256) k_final(const float* __restrict__ W2,
                                               const float* __restrict__ b2,
                                               float* __restrict__ out, int n) {
    __shared__ float W2s[HID * OUT_CH];  // 4 KB
    for (int i = threadIdx.x; i < HID * OUT_CH; i += 256) W2s[i] = W2[i];
    __syncthreads();

    int warp = threadIdx.x >> 5, lane = threadIdx.x & 31;
    int row = blockIdx.x * 8 + warp;
    if (row >= n) return;

    float di = g_dinv[row];
    float sl = di * di;
    float tk = 0.f;
    if (lane < HID)
        tk = g_agg[(size_t)row * HID + lane] + g_h1[(size_t)row * HID + lane] * sl;

    float y0 = b2[lane];
    float y1 = b2[lane + 32];
#pragma unroll
    for (int k = 0; k < HID; k++) {
        float tv = __shfl_sync(0xffffffffu, tk, k);
        y0 += tv * W2s[k * OUT_CH + lane];
        y1 += tv * W2s[k * OUT_CH + lane + 32];
    }
    // log-softmax over 64 (2 values per lane)
    float m = fmaxf(y0, y1);
#pragma unroll
    for (int o = 16; o; o >>= 1) m = fmaxf(m, __shfl_xor_sync(0xffffffffu, m, o));
    float se = expf(y0 - m) + expf(y1 - m);
#pragma unroll
    for (int o = 16; o; o >>= 1) se += __shfl_xor_sync(0xffffffffu, se, o);
    float lg = m + logf(se);
    out[(size_t)row * OUT_CH + lane] = y0 - lg;
    out[(size_t)row * OUT_CH + lane + 32] = y1 - lg;
}

// ---------------- launch ----------------
extern "C" void kernel_launch(void* const* d_in, const int* in_sizes, int n_in,
                              void* d_out, int out_size) {
    const float* x    = (const float*)d_in[0];
    const int*   ei   = (const int*)d_in[1];     // int32! (JAX x64 disabled)
    const float* W1   = (const float*)d_in[2];
    const float* b1   = (const float*)d_in[3];
    const float* W2   = (const float*)d_in[4];
    const float* b2   = (const float*)d_in[5];
    float* out        = (float*)d_out;

    const int n = in_sizes[0] / IN_CH;       // 100000
    const int e = in_sizes[1] / 2;           // 3200000
    const int* src = ei;
    const int* dst = ei + e;

    const int TB = 256;
    int gb_n   = (n + TB - 1) / TB;
    int gb_e   = (e + TB - 1) / TB;
    int gb_n16 = (n * 4 + TB - 1) / TB;      // n*16 floats / 4 per thread
    int gb_row = (n + 7) / 8;                // 8 warps (rows) per block

    k_init_deg<<<gb_n, TB>>>(n);
    k_zero_agg<<<gb_n16, TB>>>(n * 4);
    k_count_deg<<<gb_e, TB>>>(dst, e);
    k_finalize_dinv<<<gb_n, TB>>>(n);
    k_gemm1<<<(n + 255) / 256, 256>>>(x, W1, n);
    k_aggregate<<<gb_e, TB>>>(src, dst, e);
    k_epilogue1<<<gb_n16, TB>>>(b1, n);
    k_zero_agg<<<gb_n16, TB>>>(n * 4);
    k_aggregate<<<gb_e, TB>>>(src, dst, e);
    k_final<<<gb_row, 256>>>(W2, b2, out, n);
}

// round 4
// speedup vs baseline: 1.9635x; 1.9635x over previous
#include <cuda_runtime.h>
#include <cstdint>

#define N_NODES 100000
#define IN_CH   512
#define HID     16
#define OUT_CH  64
#define MAX_E   3200000

// ---------------- device scratch (static, no allocation) ----------------
__device__ float g_dinv[N_NODES];          // deg -> dinv in place
__device__ float g_h1[N_NODES * HID];      // layer1 linear out, then relu'd hidden
__device__ float g_agg[N_NODES * HID];     // aggregation buffer (reused both layers)
__device__ float g_w[MAX_E];               // per-edge normalization weight (computed pass 1)

// ---------------- kernels ----------------
__global__ void k_init_deg(int n) {
    int i = blockIdx.x * blockDim.x + threadIdx.x;
    if (i < n) g_dinv[i] = 1.0f;  // self loop
}

__global__ void k_zero_agg(int n4) {
    int i = blockIdx.x * blockDim.x + threadIdx.x;
    if (i < n4) reinterpret_cast<float4*>(g_agg)[i] = make_float4(0.f, 0.f, 0.f, 0.f);
}

__global__ void k_count_deg(const int* __restrict__ dst, int e) {
    int i = blockIdx.x * blockDim.x + threadIdx.x;
    if (i < e) atomicAdd(&g_dinv[dst[i]], 1.0f);
}

__global__ void k_finalize_dinv(int n) {
    int i = blockIdx.x * blockDim.x + threadIdx.x;
    if (i < n) g_dinv[i] = rsqrtf(g_dinv[i]);
}

// GEMM1: h1 = x @ W1   (n x 512) @ (512 x 16)
#define XT_STRIDE 260
__global__ void __launch_bounds__(256) k_gemm1(const float* __restrict__ x,
                                               const float* __restrict__ W, int n) {
    __shared__ __align__(16) float xT[16 * XT_STRIDE];  // [k][row]
    __shared__ __align__(16) float Wc[16 * HID];        // [k][j]

    const int t = threadIdx.x;
    const int rowBase = blockIdx.x * 256;
    const int jg = t & 3;
    const int rg = t >> 2;

    float acc[4][4];
#pragma unroll
    for (int r = 0; r < 4; r++)
#pragma unroll
        for (int j = 0; j < 4; j++) acc[r][j] = 0.f;

    for (int kk = 0; kk < IN_CH; kk += 16) {
        Wc[t] = W[(kk + (t >> 4)) * HID + (t & 15)];
#pragma unroll
        for (int p = 0; p < 4; p++) {
            int rlocal = (t >> 2) + p * 64;
            int k4 = (t & 3) * 4;
            int grow = rowBase + rlocal;
            float4 v = make_float4(0.f, 0.f, 0.f, 0.f);
            if (grow < n)
                v = *reinterpret_cast<const float4*>(&x[(size_t)grow * IN_CH + kk + k4]);
            xT[(k4 + 0) * XT_STRIDE + rlocal] = v.x;
            xT[(k4 + 1) * XT_STRIDE + rlocal] = v.y;
            xT[(k4 + 2) * XT_STRIDE + rlocal] = v.z;
            xT[(k4 + 3) * XT_STRIDE + rlocal] = v.w;
        }
        __syncthreads();
#pragma unroll
        for (int k = 0; k < 16; k++) {
            float4 xv = *reinterpret_cast<const float4*>(&xT[k * XT_STRIDE + rg * 4]);
            float4 wv = *reinterpret_cast<const float4*>(&Wc[k * HID + jg * 4]);
            acc[0][0] += xv.x * wv.x; acc[0][1] += xv.x * wv.y; acc[0][2] += xv.x * wv.z; acc[0][3] += xv.x * wv.w;
            acc[1][0] += xv.y * wv.x; acc[1][1] += xv.y * wv.y; acc[1][2] += xv.y * wv.z; acc[1][3] += xv.y * wv.w;
            acc[2][0] += xv.z * wv.x; acc[2][1] += xv.z * wv.y; acc[2][2] += xv.z * wv.z; acc[2][3] += xv.z * wv.w;
            acc[3][0] += xv.w * wv.x; acc[3][1] += xv.w * wv.y; acc[3][2] += xv.w * wv.z; acc[3][3] += xv.w * wv.w;
        }
        __syncthreads();
    }
#pragma unroll
    for (int r = 0; r < 4; r++) {
        int grow = rowBase + rg * 4 + r;
        if (grow < n) {
            float4 o = make_float4(acc[r][0], acc[r][1], acc[r][2], acc[r][3]);
            reinterpret_cast<float4*>(&g_h1[(size_t)grow * HID])[jg] = o;
        }
    }
}

// pass 1: compute w, store it, scatter with vector atomics
__global__ void k_aggregate_p1(const int* __restrict__ src,
                               const int* __restrict__ dst, int e) {
    int i = blockIdx.x * blockDim.x + threadIdx.x;
    if (i >= e) return;
    int s = src[i];
    int d = dst[i];
    float w = g_dinv[s] * g_dinv[d];
    g_w[i] = w;
    const float4* hp = reinterpret_cast<const float4*>(&g_h1[(size_t)s * HID]);
    float4* op = reinterpret_cast<float4*>(&g_agg[(size_t)d * HID]);
#pragma unroll
    for (int q = 0; q < 4; q++) {
        float4 v = hp[q];
        v.x *= w; v.y *= w; v.z *= w; v.w *= w;
        atomicAdd(op + q, v);
    }
}

// pass 2: reuse cached w
__global__ void k_aggregate_p2(const int* __restrict__ src,
                               const int* __restrict__ dst, int e) {
    int i = blockIdx.x * blockDim.x + threadIdx.x;
    if (i >= e) return;
    int s = src[i];
    int d = dst[i];
    float w = g_w[i];
    const float4* hp = reinterpret_cast<const float4*>(&g_h1[(size_t)s * HID]);
    float4* op = reinterpret_cast<float4*>(&g_agg[(size_t)d * HID]);
#pragma unroll
    for (int q = 0; q < 4; q++) {
        float4 v = hp[q];
        v.x *= w; v.y *= w; v.z *= w; v.w *= w;
        atomicAdd(op + q, v);
    }
}

// epilogue1: h1 = relu(agg + h1*dinv^2 + b1); also zero agg for pass 2
__global__ void k_epilogue1(const float* __restrict__ b1, int n) {
    int idx = blockIdx.x * blockDim.x + threadIdx.x;  // over n*4 float4 groups
    if (idx >= n * 4) return;
    int node = idx >> 2, q = idx & 3;
    float di = g_dinv[node];
    float sl = di * di;
    float4 a = reinterpret_cast<const float4*>(g_agg)[idx];
    float4 h = reinterpret_cast<const float4*>(g_h1)[idx];
    float4 b = reinterpret_cast<const float4*>(b1)[q];
    float4 r;
    r.x = fmaxf(a.x + h.x * sl + b.x, 0.f);
    r.y = fmaxf(a.y + h.y * sl + b.y, 0.f);
    r.z = fmaxf(a.z + h.z * sl + b.z, 0.f);
    r.w = fmaxf(a.w + h.w * sl + b.w, 0.f);
    reinterpret_cast<float4*>(g_h1)[idx] = r;
    reinterpret_cast<float4*>(g_agg)[idx] = make_float4(0.f, 0.f, 0.f, 0.f);
}

// final: t = agg + h1*dinv^2; y = t @ W2 + b2; out = log_softmax(y)
__global__ void __launch_bounds__(256) k_final(const float* __restrict__ W2,
                                               const float* __restrict__ b2,
                                               float* __restrict__ out, int n) {
    __shared__ float W2s[HID * OUT_CH];  // 4 KB
    for (int i = threadIdx.x; i < HID * OUT_CH; i += 256) W2s[i] = W2[i];
    __syncthreads();

    int warp = threadIdx.x >> 5, lane = threadIdx.x & 31;
    int row = blockIdx.x * 8 + warp;
    if (row >= n) return;

    float di = g_dinv[row];
    float sl = di * di;
    float tk = 0.f;
    if (lane < HID)
        tk = g_agg[(size_t)row * HID + lane] + g_h1[(size_t)row * HID + lane] * sl;

    float y0 = b2[lane];
    float y1 = b2[lane + 32];
#pragma unroll
    for (int k = 0; k < HID; k++) {
        float tv = __shfl_sync(0xffffffffu, tk, k);
        y0 += tv * W2s[k * OUT_CH + lane];
        y1 += tv * W2s[k * OUT_CH + lane + 32];
    }
    float m = fmaxf(y0, y1);
#pragma unroll
    for (int o = 16; o; o >>= 1) m = fmaxf(m, __shfl_xor_sync(0xffffffffu, m, o));
    float se = expf(y0 - m) + expf(y1 - m);
#pragma unroll
    for (int o = 16; o; o >>= 1) se += __shfl_xor_sync(0xffffffffu, se, o);
    float lg = m + logf(se);
    out[(size_t)row * OUT_CH + lane] = y0 - lg;
    out[(size_t)row * OUT_CH + lane + 32] = y1 - lg;
}

// ---------------- launch ----------------
extern "C" void kernel_launch(void* const* d_in, const int* in_sizes, int n_in,
                              void* d_out, int out_size) {
    const float* x    = (const float*)d_in[0];
    const int*   ei   = (const int*)d_in[1];     // int32 (JAX x64 disabled)
    const float* W1   = (const float*)d_in[2];
    const float* b1   = (const float*)d_in[3];
    const float* W2   = (const float*)d_in[4];
    const float* b2   = (const float*)d_in[5];
    float* out        = (float*)d_out;

    const int n = in_sizes[0] / IN_CH;       // 100000
    const int e = in_sizes[1] / 2;           // 3200000
    const int* src = ei;
    const int* dst = ei + e;

    const int TB = 256;
    int gb_n   = (n + TB - 1) / TB;
    int gb_e   = (e + TB - 1) / TB;
    int gb_n16 = (n * 4 + TB - 1) / TB;
    int gb_row = (n + 7) / 8;

    k_init_deg<<<gb_n, TB>>>(n);
    k_zero_agg<<<gb_n16, TB>>>(n * 4);
    k_count_deg<<<gb_e, TB>>>(dst, e);
    k_finalize_dinv<<<gb_n, TB>>>(n);
    k_gemm1<<<(n + 255) / 256, 256>>>(x, W1, n);
    k_aggregate_p1<<<gb_e, TB>>>(src, dst, e);
    k_epilogue1<<<gb_n16, TB>>>(b1, n);       // also zeroes g_agg
    k_aggregate_p2<<<gb_e, TB>>>(src, dst, e);
    k_final<<<gb_row, 256>>>(W2, b2, out, n);
}

// round 5
// speedup vs baseline: 2.7197x; 1.3851x over previous
#include <cuda_runtime.h>
#include <cstdint>

#define N_NODES 100000
#define IN_CH   512
#define HID     16
#define OUT_CH  64
#define MAX_E   3200000
#define NBLK    ((N_NODES + 255) / 256)   // 391 scan blocks

// ---------------- device scratch (static, no allocation) ----------------
__device__ float g_dinv[N_NODES];
__device__ int   g_cnt[N_NODES];
__device__ int   g_pre[N_NODES];
__device__ int   g_bsum[NBLK];
__device__ int   g_boff[NBLK];
__device__ int   g_rowptr[N_NODES + 1];
__device__ int   g_cur[N_NODES];
__device__ int2  g_csr[MAX_E];            // (src, w-bits) packed per edge, bucketed by dst
__device__ float g_h1[N_NODES * HID];     // layer1 linear out
__device__ float g_hr[N_NODES * HID];     // relu'd hidden after layer1 conv

// ---------------- CSR build ----------------
__global__ void k_zero_cnt(int n) {
    int i = blockIdx.x * blockDim.x + threadIdx.x;
    if (i < n) g_cnt[i] = 0;
}

__global__ void k_hist(const int* __restrict__ dst, int e) {
    int i = blockIdx.x * blockDim.x + threadIdx.x;
    if (i < e) atomicAdd(&g_cnt[dst[i]], 1);
}

__global__ void __launch_bounds__(256) k_scanA(int n) {
    __shared__ int s[256];
    int t = threadIdx.x;
    int i = blockIdx.x * 256 + t;
    int v = (i < n) ? g_cnt[i] : 0;
    s[t] = v;
    __syncthreads();
#pragma unroll
    for (int off = 1; off < 256; off <<= 1) {
        int add = (t >= off) ? s[t - off] : 0;
        __syncthreads();
        s[t] += add;
        __syncthreads();
    }
    if (i < n) g_pre[i] = s[t] - v;               // exclusive
    if (t == 255) g_bsum[blockIdx.x] = s[255];
}

__global__ void __launch_bounds__(512) k_scanB(int nb) {
    __shared__ int s[512];
    int t = threadIdx.x;
    int v = (t < nb) ? g_bsum[t] : 0;
    s[t] = v;
    __syncthreads();
#pragma unroll
    for (int off = 1; off < 512; off <<= 1) {
        int add = (t >= off) ? s[t - off] : 0;
        __syncthreads();
        s[t] += add;
        __syncthreads();
    }
    if (t < nb) g_boff[t] = s[t] - v;             // exclusive
}

__global__ void k_scanC(int n) {
    int i = blockIdx.x * blockDim.x + threadIdx.x;
    if (i >= n) return;
    int rp = g_pre[i] + g_boff[i >> 8];
    g_rowptr[i] = rp;
    g_cur[i] = rp;
    g_dinv[i] = rsqrtf((float)g_cnt[i] + 1.0f);   // +1 self loop
    if (i == n - 1) g_rowptr[n] = rp + g_cnt[i];
}

__global__ void k_scatter(const int* __restrict__ src,
                          const int* __restrict__ dst, int e) {
    int i = blockIdx.x * blockDim.x + threadIdx.x;
    if (i >= e) return;
    int s = src[i];
    int d = dst[i];
    float w = g_dinv[s] * g_dinv[d];
    int pos = atomicAdd(&g_cur[d], 1);
    g_csr[pos] = make_int2(s, __float_as_int(w));
}

// ---------------- GEMM1: h1 = x @ W1  (n x 512)@(512 x 16) ----------------
#define XT_STRIDE 260
__global__ void __launch_bounds__(256) k_gemm1(const float* __restrict__ x,
                                               const float* __restrict__ W, int n) {
    __shared__ __align__(16) float xT[16 * XT_STRIDE];
    __shared__ __align__(16) float Wc[16 * HID];

    const int t = threadIdx.x;
    const int rowBase = blockIdx.x * 256;
    const int jg = t & 3;
    const int rg = t >> 2;

    float acc[4][4];
#pragma unroll
    for (int r = 0; r < 4; r++)
#pragma unroll
        for (int j = 0; j < 4; j++) acc[r][j] = 0.f;

    for (int kk = 0; kk < IN_CH; kk += 16) {
        Wc[t] = W[(kk + (t >> 4)) * HID + (t & 15)];
#pragma unroll
        for (int p = 0; p < 4; p++) {
            int rlocal = (t >> 2) + p * 64;
            int k4 = (t & 3) * 4;
            int grow = rowBase + rlocal;
            float4 v = make_float4(0.f, 0.f, 0.f, 0.f);
            if (grow < n)
                v = *reinterpret_cast<const float4*>(&x[(size_t)grow * IN_CH + kk + k4]);
            xT[(k4 + 0) * XT_STRIDE + rlocal] = v.x;
            xT[(k4 + 1) * XT_STRIDE + rlocal] = v.y;
            xT[(k4 + 2) * XT_STRIDE + rlocal] = v.z;
            xT[(k4 + 3) * XT_STRIDE + rlocal] = v.w;
        }
        __syncthreads();
#pragma unroll
        for (int k = 0; k < 16; k++) {
            float4 xv = *reinterpret_cast<const float4*>(&xT[k * XT_STRIDE + rg * 4]);
            float4 wv = *reinterpret_cast<const float4*>(&Wc[k * HID + jg * 4]);
            acc[0][0] += xv.x * wv.x; acc[0][1] += xv.x * wv.y; acc[0][2] += xv.x * wv.z; acc[0][3] += xv.x * wv.w;
            acc[1][0] += xv.y * wv.x; acc[1][1] += xv.y * wv.y; acc[1][2] += xv.y * wv.z; acc[1][3] += xv.y * wv.w;
            acc[2][0] += xv.z * wv.x; acc[2][1] += xv.z * wv.y; acc[2][2] += xv.z * wv.z; acc[2][3] += xv.z * wv.w;
            acc[3][0] += xv.w * wv.x; acc[3][1] += xv.w * wv.y; acc[3][2] += xv.w * wv.z; acc[3][3] += xv.w * wv.w;
        }
        __syncthreads();
    }
#pragma unroll
    for (int r = 0; r < 4; r++) {
        int grow = rowBase + rg * 4 + r;
        if (grow < n) {
            float4 o = make_float4(acc[r][0], acc[r][1], acc[r][2], acc[r][3]);
            reinterpret_cast<float4*>(&g_h1[(size_t)grow * HID])[jg] = o;
        }
    }
}

// ---------------- gather layer 1 (fused self-loop + bias + relu) ----------------
// warp per node; quarter-warp per edge; lane owns float2 of the 16-dim vector
__global__ void __launch_bounds__(256) k_gather1(const float* __restrict__ b1, int n) {
    int wid = (blockIdx.x * 256 + threadIdx.x) >> 5;
    if (wid >= n) return;
    int lane = threadIdx.x & 31;
    int ql = lane & 7, qh = lane >> 3;
    int row = g_rowptr[wid], end = g_rowptr[wid + 1];

    float2 acc = make_float2(0.f, 0.f);
    for (int i = row + qh; i < end; i += 4) {
        int2 ec = g_csr[i];
        float w = __int_as_float(ec.y);
        float2 hv = *reinterpret_cast<const float2*>(&g_h1[(size_t)ec.x * HID + ql * 2]);
        acc.x += w * hv.x;
        acc.y += w * hv.y;
    }
    acc.x += __shfl_xor_sync(0xffffffffu, acc.x, 8);
    acc.y += __shfl_xor_sync(0xffffffffu, acc.y, 8);
    acc.x += __shfl_xor_sync(0xffffffffu, acc.x, 16);
    acc.y += __shfl_xor_sync(0xffffffffu, acc.y, 16);

    float di = g_dinv[wid];
    float sl = di * di;
    float2 hv = *reinterpret_cast<const float2*>(&g_h1[(size_t)wid * HID + ql * 2]);
    float2 bb = *reinterpret_cast<const float2*>(&b1[ql * 2]);
    float2 r;
    r.x = fmaxf(acc.x + hv.x * sl + bb.x, 0.f);
    r.y = fmaxf(acc.y + hv.y * sl + bb.y, 0.f);
    if (qh == 0)
        *reinterpret_cast<float2*>(&g_hr[(size_t)wid * HID + ql * 2]) = r;
}

// ---------------- gather layer 2 (fused W2 GEMM + log-softmax) ----------------
__global__ void __launch_bounds__(256) k_gather2(const float* __restrict__ W2,
                                                 const float* __restrict__ b2,
                                                 float* __restrict__ out, int n) {
    __shared__ float W2s[HID * OUT_CH];  // 4 KB
    for (int i = threadIdx.x; i < HID * OUT_CH; i += 256) W2s[i] = W2[i];
    __syncthreads();

    int wid = (blockIdx.x * 256 + threadIdx.x) >> 5;
    if (wid >= n) return;
    int lane = threadIdx.x & 31;
    int ql = lane & 7, qh = lane >> 3;
    int row = g_rowptr[wid], end = g_rowptr[wid + 1];

    float2 acc = make_float2(0.f, 0.f);
    for (int i = row + qh; i < end; i += 4) {
        int2 ec = g_csr[i];
        float w = __int_as_float(ec.y);
        float2 hv = *reinterpret_cast<const float2*>(&g_hr[(size_t)ec.x * HID + ql * 2]);
        acc.x += w * hv.x;
        acc.y += w * hv.y;
    }
    acc.x += __shfl_xor_sync(0xffffffffu, acc.x, 8);
    acc.y += __shfl_xor_sync(0xffffffffu, acc.y, 8);
    acc.x += __shfl_xor_sync(0xffffffffu, acc.x, 16);
    acc.y += __shfl_xor_sync(0xffffffffu, acc.y, 16);

    float di = g_dinv[wid];
    float sl = di * di;
    float2 hv = *reinterpret_cast<const float2*>(&g_hr[(size_t)wid * HID + ql * 2]);
    float tx = acc.x + hv.x * sl;   // t[2*ql]   (valid on all lanes; lane k<8 has t[2k])
    float ty = acc.y + hv.y * sl;   // t[2*ql+1]

    float y0 = b2[lane];
    float y1 = b2[lane + 32];
#pragma unroll
    for (int k = 0; k < 8; k++) {
        float a = __shfl_sync(0xffffffffu, tx, k);
        float b = __shfl_sync(0xffffffffu, ty, k);
        y0 += a * W2s[(2 * k) * OUT_CH + lane]      + b * W2s[(2 * k + 1) * OUT_CH + lane];
        y1 += a * W2s[(2 * k) * OUT_CH + lane + 32] + b * W2s[(2 * k + 1) * OUT_CH + lane + 32];
    }
    float m = fmaxf(y0, y1);
#pragma unroll
    for (int o = 16; o; o >>= 1) m = fmaxf(m, __shfl_xor_sync(0xffffffffu, m, o));
    float se = expf(y0 - m) + expf(y1 - m);
#pragma unroll
    for (int o = 16; o; o >>= 1) se += __shfl_xor_sync(0xffffffffu, se, o);
    float lg = m + logf(se);
    out[(size_t)wid * OUT_CH + lane]      = y0 - lg;
    out[(size_t)wid * OUT_CH + lane + 32] = y1 - lg;
}

// ---------------- launch ----------------
extern "C" void kernel_launch(void* const* d_in, const int* in_sizes, int n_in,
                              void* d_out, int out_size) {
    const float* x    = (const float*)d_in[0];
    const int*   ei   = (const int*)d_in[1];     // int32 (JAX x64 disabled)
    const float* W1   = (const float*)d_in[2];
    const float* b1   = (const float*)d_in[3];
    const float* W2   = (const float*)d_in[4];
    const float* b2   = (const float*)d_in[5];
    float* out        = (float*)d_out;

    const int n = in_sizes[0] / IN_CH;       // 100000
    const int e = in_sizes[1] / 2;           // 3200000
    const int* src = ei;
    const int* dst = ei + e;

    const int TB = 256;
    int gb_n = (n + TB - 1) / TB;            // == NBLK
    int gb_e = (e + TB - 1) / TB;
    int gb_w = (n * 32 + TB - 1) / TB;       // warp-per-node kernels

    k_zero_cnt<<<gb_n, TB>>>(n);
    k_hist<<<gb_e, TB>>>(dst, e);
    k_scanA<<<gb_n, TB>>>(n);
    k_scanB<<<1, 512>>>(gb_n);
    k_scanC<<<gb_n, TB>>>(n);
    k_scatter<<<gb_e, TB>>>(src, dst, e);
    k_gemm1<<<(n + 255) / 256, 256>>>(x, W1, n);
    k_gather1<<<gb_w, TB>>>(b1, n);
    k_gather2<<<gb_w, TB>>>(W2, b2, out, n);
}